// round 8
// baseline (speedup 1.0000x reference)
#include <cuda_runtime.h>
#include <math.h>

#define HHv 83
#define WWv 25
#define AAv 9
#define N_ANCH (HHv*WWv*AAv)   /* 18675 */
#define BATCH 16
#define PRE 12000
#define POST 2000
#define MIN_SIZE 16.0f
#define NMS_T 0.7f
#define IMG_XF 1333.0f
#define IMG_YF 402.0f
#define FLIP_NEG_INF 0x007FFFFFu
#define CHUNK 64
#define NMS_THREADS 1024

#define K_BIN   1.90f
#define NBW     13
#define NBH     10
#define BIN_OFF 7
#define NCELLS  (NBW*NBH)      /* 130 */
#define BINCAP  256
#define SPILLCAP 2048

__device__ float4   g_boxes[BATCH * N_ANCH];
__device__ unsigned g_skey [BATCH * N_ANCH];
__device__ float4   g_candBox[BATCH * PRE];
__device__ int      g_candCount[BATCH];

__device__ __forceinline__ unsigned flipf(float f){
    unsigned u = __float_as_uint(f);
    return (u & 0x80000000u) ? ~u : (u | 0x80000000u);
}

// ---------------------------------------------------------------- K1: decode
__global__ void k_decode(const float4* __restrict__ anchors,
                         const float*  __restrict__ cls,
                         const float4* __restrict__ pred)
{
    int t = blockIdx.x*blockDim.x + threadIdx.x;
    if (t >= BATCH*N_ANCH) return;
    int b = t / N_ANCH, i = t - b*N_ANCH;

    float4 a = anchors[i];
    float ah  = __fsub_rn(a.w, a.y);
    float aw  = __fsub_rn(a.z, a.x);
    float acy = __fadd_rn(a.y, __fmul_rn(0.5f, ah));
    float acx = __fadd_rn(a.x, __fmul_rn(0.5f, aw));

    float4 p = pred[t];   // dx, dy, dw, dh
    float cy = __fadd_rn(__fmul_rn(p.y, ah), acy);
    float cx = __fadd_rn(__fmul_rn(p.x, aw), acx);
    float eh = (float)exp((double)p.w);
    float ew = (float)exp((double)p.z);
    float h  = __fmul_rn(eh, ah);
    float w  = __fmul_rn(ew, aw);

    float hw = __fmul_rn(0.5f, w);
    float hh = __fmul_rn(0.5f, h);
    float x1 = fminf(fmaxf(__fsub_rn(cx, hw), 0.f), IMG_XF);
    float y1 = fminf(fmaxf(__fsub_rn(cy, hh), 0.f), IMG_YF);
    float x2 = fminf(fmaxf(__fadd_rn(cx, hw), 0.f), IMG_XF);
    float y2 = fminf(fmaxf(__fadd_rn(cy, hh), 0.f), IMG_YF);

    g_boxes[t] = make_float4(x1, y1, x2, y2);

    bool valid = (__fsub_rn(y2, y1) >= MIN_SIZE) && (__fsub_rn(x2, x1) >= MIN_SIZE);
    float s = valid ? cls[b*(2*N_ANCH) + 2*i + 1] : -INFINITY;
    g_skey[t] = flipf(s);
}

// -------------------------------------------- K2: exact top-PRE select + compact
__device__ __forceinline__ void thresh_desc(const int* hist, int nb, int target,
                                            int tid, int lane, int wid,
                                            int* s_wsum, int* s_out)
{
    int half = nb >> 1;
    int h0=0, h1=0;
    if (tid < half){
        h0 = hist[nb-1-2*tid];
        h1 = hist[nb-2-2*tid];
    }
    int local = h0+h1, v = local;
    #pragma unroll
    for (int off=1; off<32; off<<=1){
        int nv = __shfl_up_sync(0xffffffffu, v, off);
        if (lane >= off) v += nv;
    }
    if (lane==31) s_wsum[wid] = v;
    __syncthreads();
    if (wid==0){
        int wv = s_wsum[lane];
        int sv = wv;
        #pragma unroll
        for (int off=1; off<32; off<<=1){
            int nv = __shfl_up_sync(0xffffffffu, sv, off);
            if (lane >= off) sv += nv;
        }
        s_wsum[lane] = sv - wv;
    }
    __syncthreads();
    int incl = v + s_wsum[wid];
    int excl = incl - local;
    if (tid < half){
        if (excl < target && excl + h0 >= target){
            s_out[0] = nb-1-2*tid; s_out[1] = target - excl;
        } else if (excl + h0 < target && excl + h0 + h1 >= target){
            s_out[0] = nb-2-2*tid; s_out[1] = target - excl - h0;
        }
    }
    __syncthreads();
}

__global__ void __launch_bounds__(1024) k_select()
{
    int b = blockIdx.x;
    const unsigned* skey = g_skey + b*N_ANCH;
    const int BD = 1024;
    int tid = threadIdx.x;
    int lane = tid & 31, wid = tid >> 5;

    __shared__ int      hist[2048];
    __shared__ int      s_wsum[32];
    __shared__ int      s_out[2];
    __shared__ unsigned s_T;
    __shared__ int      s_binI, s_rr, s_eqN, s_Tidx;
    __shared__ int      s_eqIdx[32];

    for (int j=tid;j<2048;j+=BD) hist[j]=0;
    __syncthreads();
    for (int i=tid;i<N_ANCH;i+=BD) atomicAdd(&hist[skey[i]>>21], 1);
    __syncthreads();
    thresh_desc(hist, 2048, PRE, tid, lane, wid, s_wsum, s_out);
    unsigned b0 = (unsigned)s_out[0];
    int r = s_out[1];
    __syncthreads();

    for (int j=tid;j<2048;j+=BD) hist[j]=0;
    __syncthreads();
    for (int i=tid;i<N_ANCH;i+=BD){
        unsigned k=skey[i];
        if ((k>>21)==b0) atomicAdd(&hist[(k>>10)&0x7FFu],1);
    }
    __syncthreads();
    thresh_desc(hist, 2048, r, tid, lane, wid, s_wsum, s_out);
    unsigned pfx = (b0<<11) | (unsigned)s_out[0];
    r = s_out[1];
    __syncthreads();

    for (int j=tid;j<1024;j+=BD) hist[j]=0;
    __syncthreads();
    for (int i=tid;i<N_ANCH;i+=BD){
        unsigned k=skey[i];
        if ((k>>10)==pfx) atomicAdd(&hist[k&0x3FFu],1);
    }
    __syncthreads();
    thresh_desc(hist, 1024, r, tid, lane, wid, s_wsum, s_out);
    unsigned T = (pfx<<10) | (unsigned)s_out[0];
    r = s_out[1];
    int cEq = hist[s_out[0]];
    if (tid==0) s_T = T;
    __syncthreads();
    T = s_T;

    int Tidx;
    if (r >= cEq){
        Tidx = N_ANCH;
    } else {
        for (int j=tid;j<2048;j+=BD) hist[j]=0;
        __syncthreads();
        for (int i=tid;i<N_ANCH;i+=BD)
            if (skey[i]==T) atomicAdd(&hist[i>>4],1);
        __syncthreads();
        if (tid==0){
            int cum=0, binI=0, rr=r;
            for (int bin=0;bin<2048;++bin){
                int c=hist[bin];
                if (cum+c>=r){ binI=bin; rr=r-cum; break; }
                cum+=c;
            }
            s_binI=binI; s_rr=rr; s_eqN=0;
        }
        __syncthreads();
        int binI=s_binI;
        for (int i=tid;i<N_ANCH;i+=BD)
            if (skey[i]==T && (i>>4)==binI){
                int p=atomicAdd(&s_eqN,1);
                s_eqIdx[p]=i;
            }
        __syncthreads();
        if (tid==0){
            int n=s_eqN, need=s_rr;
            for (int a2=0;a2<n;a2++)
                for (int b2=a2+1;b2<n;b2++)
                    if (s_eqIdx[b2]<s_eqIdx[a2]){
                        int tmp=s_eqIdx[a2]; s_eqIdx[a2]=s_eqIdx[b2]; s_eqIdx[b2]=tmp;
                    }
            s_Tidx = s_eqIdx[need-1];
        }
        __syncthreads();
        Tidx = s_Tidx;
    }

    __shared__ int s_wcnt[32];
    const float4* boxes = g_boxes   + b*N_ANCH;
    float4*       cand  = g_candBox + b*PRE;
    int nCh = (N_ANCH + BD - 1)/BD;
    int running = 0;

    for (int c=0;c<nCh;c++){
        int pos = c*BD + tid;
        int i = N_ANCH-1-pos;
        bool pred=false;
        if (i>=0){
            unsigned k = skey[i];
            bool valid = (k != FLIP_NEG_INF);
            bool sel   = (k > T) || (k==T && i<=Tidx);
            pred = valid && sel;
        }
        unsigned bal = __ballot_sync(0xffffffffu, pred);
        if (lane==0) s_wcnt[wid]=__popc(bal);
        __syncthreads();
        int base = running, tot = 0;
        #pragma unroll
        for (int w2=0;w2<32;w2++){
            int cnt = s_wcnt[w2];
            if (w2 < wid) base += cnt;
            tot += cnt;
        }
        if (pred){
            int p = base + __popc(bal & ((1u<<lane)-1u));
            cand[p] = boxes[i];
        }
        running += tot;
        __syncthreads();
    }
    if (tid==0) g_candCount[b]=running;
}

// ---------------------------------------------------------------- K3: greedy NMS
__device__ __forceinline__ bool iou_sup(const float4& A, float aA,
                                        const float4& Bx, float aB)
{
    float xx1=fmaxf(A.x,Bx.x), yy1=fmaxf(A.y,Bx.y);
    float xx2=fminf(A.z,Bx.z), yy2=fminf(A.w,Bx.w);
    float iw=fmaxf(__fadd_rn(__fsub_rn(xx2,xx1),1.f),0.f);
    float ih=fmaxf(__fadd_rn(__fsub_rn(yy2,yy1),1.f),0.f);
    float inter=__fmul_rn(iw,ih);
    float uni = __fsub_rn(__fadd_rn(aA,aB), inter);
    float t   = __fmul_rn(NMS_T, uni);
    if (inter > __fmul_rn(t, 1.0000010f)) return true;
    if (inter < __fmul_rn(t, 0.9999990f)) return false;
    return __fdiv_rn(inter, uni) > NMS_T;
}

__device__ __forceinline__ int bin_of(float v){
    int bn = (int)floorf(__fmul_rn(__log2f(v), K_BIN)) - BIN_OFF;
    return bn;
}

// dynamic smem layout (bytes)
#define SO_KB     0                              /* float4[2000] = 32000 */
#define SO_KA     32000                          /* float[2000]  =  8000 */
#define SO_CELL   40000                          /* u16[130*256] = 66560 */
#define SO_SPILL  106560                         /* u16[2048]    =  4096 */
#define SO_CBOX   110656                         /* float4[64]   =  1024 */
#define SO_CAREA  111680                         /* float[64]    =   256 */
#define SO_CWB    111936                         /* u8[64]       =    64 */
#define SO_CHB    112000                         /* u8[64]       =    64 */
#define SO_MAT    112064                         /* u64[64]      =   512 */
#define SO_SUP    112576                         /* u8[64]       =    64 */
#define SO_NEW    112640                         /* int[64]      =   256 */
#define SO_BCNT   112896                         /* int[130]     =   520 */
#define SMEM_NMS  113472

__global__ void __launch_bounds__(NMS_THREADS)
k_nms(float* __restrict__ outRois, float* __restrict__ outMask, int writeMask)
{
    extern __shared__ unsigned char sm[];
    float4*             kb      = (float4*)(sm + SO_KB);
    float*              ka      = (float*)(sm + SO_KA);
    unsigned short*     cells   = (unsigned short*)(sm + SO_CELL);
    unsigned short*     spill   = (unsigned short*)(sm + SO_SPILL);
    float4*             cbox    = (float4*)(sm + SO_CBOX);
    float*              carea   = (float*)(sm + SO_CAREA);
    unsigned char*      cwb     = sm + SO_CWB;
    unsigned char*      chb     = sm + SO_CHB;
    unsigned long long* s_mat   = (unsigned long long*)(sm + SO_MAT);
    unsigned char*      s_sup   = sm + SO_SUP;
    int*                s_new   = (int*)(sm + SO_NEW);
    int*                s_bcnt  = (int*)(sm + SO_BCNT);

    __shared__ int s_nn, s_kept, s_spillCnt;

    int b    = blockIdx.x;
    int tid  = threadIdx.x;
    int lane = tid & 31;
    int wid  = tid >> 5;
    int nc   = g_candCount[b];
    const float4* cand = g_candBox + b*PRE;
    const unsigned FULL = 0xffffffffu;

    float4 creg = make_float4(0.f,0.f,0.f,0.f);
    if (tid < CHUNK && tid < nc) creg = cand[tid];
    if (tid==0){ s_kept = 0; s_spillCnt = 0; }
    for (int j=tid; j<NCELLS; j+=NMS_THREADS) s_bcnt[j] = 0;
    __syncthreads();

    for (int start=0; start<nc; start+=CHUNK){
        int kept = s_kept;
        if (kept >= POST) break;
        int n = min(CHUNK, nc-start);

        // ---- phase A: stage prefetched candidates, compute area + 2D bins
        if (tid < CHUNK && tid < n){
            float w = __fadd_rn(__fsub_rn(creg.z, creg.x), 1.f);
            float h = __fadd_rn(__fsub_rn(creg.w, creg.y), 1.f);
            cbox[tid]  = creg;
            carea[tid] = __fmul_rn(w, h);
            cwb[tid]   = (unsigned char)min(max(bin_of(w), 0), NBW-1);
            chb[tid]   = (unsigned char)min(max(bin_of(h), 0), NBH-1);
        }
        __syncthreads();                       // (1)

        // prefetch next chunk
        {
            int nxt = start + CHUNK + tid;
            if (tid < CHUNK && nxt < nc) creg = cand[nxt];
        }

        // ---- phase B1: 64x64 forward matrix (16 threads per candidate)
        {
            int c   = tid >> 4;
            int sub = tid & 15;
            unsigned long long m = 0ull;
            if (c < n){
                float4 A = cbox[c]; float aA = carea[c];
                for (int c2 = c+1+sub; c2 < n; c2 += 16){
                    float aB = carea[c2];
                    if (fminf(aA,aB) >= __fmul_rn(0.695f, fmaxf(aA,aB)))
                        if (iou_sup(A, aA, cbox[c2], aB)) m |= 1ull << c2;
                }
            }
            #pragma unroll
            for (int off=8; off>0; off>>=1)
                m |= __shfl_xor_sync(FULL, m, off);
            if ((lane & 15)==0) s_mat[c] = m;
        }

        // ---- phase B2: warp-per-candidate vs 3x3 cell neighborhood
        {
            int spillN = s_spillCnt;
            for (int cc = wid; cc < CHUNK; cc += 32){
                bool activeC = (cc < n);
                bool f = false;
                if (activeC){
                    float4 A = cbox[cc];
                    float aA = carea[cc];
                    int wb = cwb[cc], hb = chb[cc];
                    int wlo = max(wb-1,0), whi = min(wb+1,NBW-1);
                    int hlo = max(hb-1,0), hhi = min(hb+1,NBH-1);
                    bool anyf = false;
                    for (int ww=wlo; ww<=whi && !anyf; ww++){
                        for (int hh2=hlo; hh2<=hhi && !anyf; hh2++){
                            int cell = ww*NBH + hh2;
                            int L = s_bcnt[cell];
                            const unsigned short* lst = cells + cell*BINCAP;
                            for (int j=lane; __any_sync(FULL, j<L); j+=32){
                                bool t=false;
                                if (j < L && !f){
                                    int kj = lst[j];
                                    float aB = ka[kj];
                                    if (fminf(aA,aB) >= __fmul_rn(0.695f, fmaxf(aA,aB)))
                                        t = iou_sup(A, aA, kb[kj], aB);
                                }
                                f |= t;
                                if (__any_sync(FULL, f)) break;
                            }
                            anyf = __any_sync(FULL, f);
                        }
                    }
                    if (!anyf){
                        for (int j=lane; __any_sync(FULL, j<spillN); j+=32){
                            bool t=false;
                            if (j < spillN && !f){
                                int kj = spill[j];
                                float aB = ka[kj];
                                if (fminf(aA,aB) >= __fmul_rn(0.695f, fmaxf(aA,aB)))
                                    t = iou_sup(A, aA, kb[kj], aB);
                            }
                            f |= t;
                            if (__any_sync(FULL, f)) break;
                        }
                    }
                }
                bool supC = __any_sync(FULL, f);
                if (lane==0) s_sup[cc] = supC ? 1 : 0;
            }
        }
        __syncthreads();                       // (2)

        // ---- phase C: warp-0 register-resident greedy resolve
        if (wid==0){
            unsigned lo = __ballot_sync(FULL, s_sup[lane] != 0);
            unsigned hi = __ballot_sync(FULL, s_sup[lane+32] != 0);
            unsigned long long sup = (unsigned long long)lo |
                                     ((unsigned long long)hi << 32);
            unsigned long long m0 = s_mat[lane];
            unsigned long long m1 = s_mat[lane+32];
            unsigned long long rem = ~sup;
            if (n < 64) rem &= (1ull<<n) - 1ull;
            int nn = 0;
            while (rem != 0ull && kept+nn < POST){
                int c = __ffsll((long long)rem) - 1;
                if (lane==0) s_new[nn] = c;
                nn++;
                unsigned long long mc = __shfl_sync(FULL, (c<32)? m0 : m1, c & 31);
                rem &= ~mc;
                rem &= ~(1ull << c);
            }
            if (lane==0){ s_nn = nn; s_kept = kept + nn; }
        }
        __syncthreads();                       // (3)

        // ---- phase D: append keeps into cells + write outputs
        int nn = s_nn;
        if (tid < nn){
            int cc = s_new[tid];
            float4 bx = cbox[cc];
            float a  = carea[cc];
            int ki = kept + tid;
            kb[ki] = bx;
            ka[ki] = a;
            int cell = (int)cwb[cc]*NBH + (int)chb[cc];
            int slot = atomicAdd(&s_bcnt[cell], 1);
            if (slot < BINCAP){
                cells[cell*BINCAP + slot] = (unsigned short)ki;
            } else {
                atomicSub(&s_bcnt[cell], 1);
                int sp = atomicAdd(&s_spillCnt, 1);
                spill[sp] = (unsigned short)ki;
            }
            int row = b*POST + ki;
            ((float4*)outRois)[row] = bx;
            if (writeMask) outMask[row] = 1.0f;
        }
        __syncthreads();                       // (4)
    }

    // ---- zero-fill tail
    int kept = s_kept;
    for (int rrow = kept + tid; rrow < POST; rrow += NMS_THREADS){
        int row = b*POST + rrow;
        ((float4*)outRois)[row] = make_float4(0.f,0.f,0.f,0.f);
        if (writeMask) outMask[row] = 0.f;
    }
}

// ---------------------------------------------------------------- launch
extern "C" void kernel_launch(void* const* d_in, const int* in_sizes, int n_in,
                              void* d_out, int out_size)
{
    (void)in_sizes; (void)n_in;
    const float4* anchors = (const float4*)d_in[0];
    const float*  cls     = (const float*)d_in[1];
    const float4* pred    = (const float4*)d_in[2];
    float* out = (float*)d_out;

    cudaFuncSetAttribute(k_nms, cudaFuncAttributeMaxDynamicSharedMemorySize, SMEM_NMS);

    int total = BATCH*N_ANCH;
    k_decode<<<(total+255)/256, 256>>>(anchors, cls, pred);
    k_select<<<BATCH, 1024>>>();

    int writeMask = (out_size >= BATCH*POST*5) ? 1 : 0;
    k_nms<<<BATCH, NMS_THREADS, SMEM_NMS>>>(out, out + BATCH*POST*4, writeMask);
}

// round 9
// speedup vs baseline: 1.1237x; 1.1237x over previous
#include <cuda_runtime.h>
#include <math.h>

#define HHv 83
#define WWv 25
#define AAv 9
#define N_ANCH (HHv*WWv*AAv)   /* 18675 */
#define BATCH 16
#define PRE 12000
#define POST 2000
#define MIN_SIZE 16.0f
#define NMS_T 0.7f
#define IMG_XF 1333.0f
#define IMG_YF 402.0f
#define FLIP_NEG_INF 0x007FFFFFu
#define CHUNK 64
#define NMS_THREADS 1024

#define K_BIN   1.90f
#define NBW     13
#define NBH     10
#define BIN_OFF 7
#define NCELLS  (NBW*NBH)      /* 130 */
#define BINCAP  256
#define SPILLCAP 2048

__device__ float4   g_boxes[BATCH * N_ANCH];
__device__ unsigned g_skey [BATCH * N_ANCH];
__device__ float4   g_candBox[BATCH * PRE];
__device__ int      g_candCount[BATCH];

__device__ __forceinline__ unsigned flipf(float f){
    unsigned u = __float_as_uint(f);
    return (u & 0x80000000u) ? ~u : (u | 0x80000000u);
}

// ---------------------------------------------------------------- K1: decode
__global__ void k_decode(const float4* __restrict__ anchors,
                         const float*  __restrict__ cls,
                         const float4* __restrict__ pred)
{
    int t = blockIdx.x*blockDim.x + threadIdx.x;
    if (t >= BATCH*N_ANCH) return;
    int b = t / N_ANCH, i = t - b*N_ANCH;

    float4 a = anchors[i];
    float ah  = __fsub_rn(a.w, a.y);
    float aw  = __fsub_rn(a.z, a.x);
    float acy = __fadd_rn(a.y, __fmul_rn(0.5f, ah));
    float acx = __fadd_rn(a.x, __fmul_rn(0.5f, aw));

    float4 p = pred[t];   // dx, dy, dw, dh
    float cy = __fadd_rn(__fmul_rn(p.y, ah), acy);
    float cx = __fadd_rn(__fmul_rn(p.x, aw), acx);
    float eh = (float)exp((double)p.w);
    float ew = (float)exp((double)p.z);
    float h  = __fmul_rn(eh, ah);
    float w  = __fmul_rn(ew, aw);

    float hw = __fmul_rn(0.5f, w);
    float hh = __fmul_rn(0.5f, h);
    float x1 = fminf(fmaxf(__fsub_rn(cx, hw), 0.f), IMG_XF);
    float y1 = fminf(fmaxf(__fsub_rn(cy, hh), 0.f), IMG_YF);
    float x2 = fminf(fmaxf(__fadd_rn(cx, hw), 0.f), IMG_XF);
    float y2 = fminf(fmaxf(__fadd_rn(cy, hh), 0.f), IMG_YF);

    g_boxes[t] = make_float4(x1, y1, x2, y2);

    bool valid = (__fsub_rn(y2, y1) >= MIN_SIZE) && (__fsub_rn(x2, x1) >= MIN_SIZE);
    float s = valid ? cls[b*(2*N_ANCH) + 2*i + 1] : -INFINITY;
    g_skey[t] = flipf(s);
}

// -------------------------------------------- K2: exact top-PRE select + compact
__device__ __forceinline__ void thresh_desc(const int* hist, int nb, int target,
                                            int tid, int lane, int wid,
                                            int* s_wsum, int* s_out)
{
    int half = nb >> 1;
    int h0=0, h1=0;
    if (tid < half){
        h0 = hist[nb-1-2*tid];
        h1 = hist[nb-2-2*tid];
    }
    int local = h0+h1, v = local;
    #pragma unroll
    for (int off=1; off<32; off<<=1){
        int nv = __shfl_up_sync(0xffffffffu, v, off);
        if (lane >= off) v += nv;
    }
    if (lane==31) s_wsum[wid] = v;
    __syncthreads();
    if (wid==0){
        int wv = s_wsum[lane];
        int sv = wv;
        #pragma unroll
        for (int off=1; off<32; off<<=1){
            int nv = __shfl_up_sync(0xffffffffu, sv, off);
            if (lane >= off) sv += nv;
        }
        s_wsum[lane] = sv - wv;
    }
    __syncthreads();
    int incl = v + s_wsum[wid];
    int excl = incl - local;
    if (tid < half){
        if (excl < target && excl + h0 >= target){
            s_out[0] = nb-1-2*tid; s_out[1] = target - excl;
        } else if (excl + h0 < target && excl + h0 + h1 >= target){
            s_out[0] = nb-2-2*tid; s_out[1] = target - excl - h0;
        }
    }
    __syncthreads();
}

__global__ void __launch_bounds__(1024) k_select()
{
    int b = blockIdx.x;
    const unsigned* skey = g_skey + b*N_ANCH;
    const int BD = 1024;
    int tid = threadIdx.x;
    int lane = tid & 31, wid = tid >> 5;

    __shared__ int      hist[2048];
    __shared__ int      s_wsum[32];
    __shared__ int      s_out[2];
    __shared__ unsigned s_T;
    __shared__ int      s_binI, s_rr, s_eqN, s_Tidx;
    __shared__ int      s_eqIdx[32];

    for (int j=tid;j<2048;j+=BD) hist[j]=0;
    __syncthreads();
    for (int i=tid;i<N_ANCH;i+=BD) atomicAdd(&hist[skey[i]>>21], 1);
    __syncthreads();
    thresh_desc(hist, 2048, PRE, tid, lane, wid, s_wsum, s_out);
    unsigned b0 = (unsigned)s_out[0];
    int r = s_out[1];
    __syncthreads();

    for (int j=tid;j<2048;j+=BD) hist[j]=0;
    __syncthreads();
    for (int i=tid;i<N_ANCH;i+=BD){
        unsigned k=skey[i];
        if ((k>>21)==b0) atomicAdd(&hist[(k>>10)&0x7FFu],1);
    }
    __syncthreads();
    thresh_desc(hist, 2048, r, tid, lane, wid, s_wsum, s_out);
    unsigned pfx = (b0<<11) | (unsigned)s_out[0];
    r = s_out[1];
    __syncthreads();

    for (int j=tid;j<1024;j+=BD) hist[j]=0;
    __syncthreads();
    for (int i=tid;i<N_ANCH;i+=BD){
        unsigned k=skey[i];
        if ((k>>10)==pfx) atomicAdd(&hist[k&0x3FFu],1);
    }
    __syncthreads();
    thresh_desc(hist, 1024, r, tid, lane, wid, s_wsum, s_out);
    unsigned T = (pfx<<10) | (unsigned)s_out[0];
    r = s_out[1];
    int cEq = hist[s_out[0]];
    if (tid==0) s_T = T;
    __syncthreads();
    T = s_T;

    int Tidx;
    if (r >= cEq){
        Tidx = N_ANCH;
    } else {
        for (int j=tid;j<2048;j+=BD) hist[j]=0;
        __syncthreads();
        for (int i=tid;i<N_ANCH;i+=BD)
            if (skey[i]==T) atomicAdd(&hist[i>>4],1);
        __syncthreads();
        if (tid==0){
            int cum=0, binI=0, rr=r;
            for (int bin=0;bin<2048;++bin){
                int c=hist[bin];
                if (cum+c>=r){ binI=bin; rr=r-cum; break; }
                cum+=c;
            }
            s_binI=binI; s_rr=rr; s_eqN=0;
        }
        __syncthreads();
        int binI=s_binI;
        for (int i=tid;i<N_ANCH;i+=BD)
            if (skey[i]==T && (i>>4)==binI){
                int p=atomicAdd(&s_eqN,1);
                s_eqIdx[p]=i;
            }
        __syncthreads();
        if (tid==0){
            int n=s_eqN, need=s_rr;
            for (int a2=0;a2<n;a2++)
                for (int b2=a2+1;b2<n;b2++)
                    if (s_eqIdx[b2]<s_eqIdx[a2]){
                        int tmp=s_eqIdx[a2]; s_eqIdx[a2]=s_eqIdx[b2]; s_eqIdx[b2]=tmp;
                    }
            s_Tidx = s_eqIdx[need-1];
        }
        __syncthreads();
        Tidx = s_Tidx;
    }

    __shared__ int s_wcnt[32];
    const float4* boxes = g_boxes   + b*N_ANCH;
    float4*       cand  = g_candBox + b*PRE;
    int nCh = (N_ANCH + BD - 1)/BD;
    int running = 0;

    for (int c=0;c<nCh;c++){
        int pos = c*BD + tid;
        int i = N_ANCH-1-pos;
        bool pred=false;
        if (i>=0){
            unsigned k = skey[i];
            bool valid = (k != FLIP_NEG_INF);
            bool sel   = (k > T) || (k==T && i<=Tidx);
            pred = valid && sel;
        }
        unsigned bal = __ballot_sync(0xffffffffu, pred);
        if (lane==0) s_wcnt[wid]=__popc(bal);
        __syncthreads();
        int base = running, tot = 0;
        #pragma unroll
        for (int w2=0;w2<32;w2++){
            int cnt = s_wcnt[w2];
            if (w2 < wid) base += cnt;
            tot += cnt;
        }
        if (pred){
            int p = base + __popc(bal & ((1u<<lane)-1u));
            cand[p] = boxes[i];
        }
        running += tot;
        __syncthreads();
    }
    if (tid==0) g_candCount[b]=running;
}

// ---------------------------------------------------------------- K3: greedy NMS
__device__ __forceinline__ bool iou_sup(const float4& A, float aA,
                                        const float4& Bx, float aB)
{
    float xx1=fmaxf(A.x,Bx.x), yy1=fmaxf(A.y,Bx.y);
    float xx2=fminf(A.z,Bx.z), yy2=fminf(A.w,Bx.w);
    float iw=fmaxf(__fadd_rn(__fsub_rn(xx2,xx1),1.f),0.f);
    float ih=fmaxf(__fadd_rn(__fsub_rn(yy2,yy1),1.f),0.f);
    float inter=__fmul_rn(iw,ih);
    float uni = __fsub_rn(__fadd_rn(aA,aB), inter);
    float t   = __fmul_rn(NMS_T, uni);
    if (inter > __fmul_rn(t, 1.0000010f)) return true;
    if (inter < __fmul_rn(t, 0.9999990f)) return false;
    return __fdiv_rn(inter, uni) > NMS_T;
}

__device__ __forceinline__ int bin_of(float v){
    int bn = (int)floorf(__fmul_rn(__log2f(v), K_BIN)) - BIN_OFF;
    return bn;
}

// dynamic smem layout (bytes)
#define SO_KB     0                              /* float4[2000] = 32000 */
#define SO_KA     32000                          /* float[2000]  =  8000 */
#define SO_CELL   40000                          /* u16[130*256] = 66560 */
#define SO_SPILL  106560                         /* u16[2048]    =  4096 */
#define SO_CBOX   110656                         /* float4[64]   =  1024 */
#define SO_CAREA  111680                         /* float[64]    =   256 */
#define SO_CWB    111936                         /* u8[64]       =    64 */
#define SO_CHB    112000                         /* u8[64]       =    64 */
#define SO_MAT    112064                         /* u64[64]      =   512 */
#define SO_SUP    112576                         /* u8[64]       =    64 */
#define SO_NEW    112640                         /* int[64]      =   256 */
#define SO_BCNT   112896                         /* int[130]     =   520 */
#define SMEM_NMS  113472

__global__ void __launch_bounds__(NMS_THREADS)
k_nms(float* __restrict__ outRois, float* __restrict__ outMask, int writeMask)
{
    extern __shared__ unsigned char sm[];
    float4*             kb      = (float4*)(sm + SO_KB);
    float*              ka      = (float*)(sm + SO_KA);
    unsigned short*     cells   = (unsigned short*)(sm + SO_CELL);
    unsigned short*     spill   = (unsigned short*)(sm + SO_SPILL);
    float4*             cbox    = (float4*)(sm + SO_CBOX);
    float*              carea   = (float*)(sm + SO_CAREA);
    unsigned char*      cwb     = sm + SO_CWB;
    unsigned char*      chb     = sm + SO_CHB;
    unsigned long long* s_mat   = (unsigned long long*)(sm + SO_MAT);
    unsigned char*      s_sup   = sm + SO_SUP;
    int*                s_new   = (int*)(sm + SO_NEW);
    int*                s_bcnt  = (int*)(sm + SO_BCNT);

    __shared__ int s_nn, s_kept, s_spillCnt;

    int b    = blockIdx.x;
    int tid  = threadIdx.x;
    int lane = tid & 31;
    int wid  = tid >> 5;
    int nc   = g_candCount[b];
    const float4* cand = g_candBox + b*PRE;
    const unsigned FULL = 0xffffffffu;

    float4 creg = make_float4(0.f,0.f,0.f,0.f);
    if (tid < CHUNK && tid < nc) creg = cand[tid];
    if (tid==0){ s_kept = 0; s_spillCnt = 0; }
    for (int j=tid; j<NCELLS; j+=NMS_THREADS) s_bcnt[j] = 0;
    __syncthreads();

    for (int start=0; start<nc; start+=CHUNK){
        int kept = s_kept;
        if (kept >= POST) break;
        int n = min(CHUNK, nc-start);

        // ---- phase A: stage prefetched candidates, compute area + 2D bins
        if (tid < CHUNK && tid < n){
            float w = __fadd_rn(__fsub_rn(creg.z, creg.x), 1.f);
            float h = __fadd_rn(__fsub_rn(creg.w, creg.y), 1.f);
            cbox[tid]  = creg;
            carea[tid] = __fmul_rn(w, h);
            cwb[tid]   = (unsigned char)min(max(bin_of(w), 0), NBW-1);
            chb[tid]   = (unsigned char)min(max(bin_of(h), 0), NBH-1);
        }
        __syncthreads();                       // (1)

        // prefetch next chunk
        {
            int nxt = start + CHUNK + tid;
            if (tid < CHUNK && nxt < nc) creg = cand[nxt];
        }

        // ---- phase B1: 64x64 forward matrix (16 threads per candidate)
        {
            int c   = tid >> 4;
            int sub = tid & 15;
            unsigned long long m = 0ull;
            if (c < n){
                float4 A = cbox[c]; float aA = carea[c];
                for (int c2 = c+1+sub; c2 < n; c2 += 16){
                    float aB = carea[c2];
                    if (fminf(aA,aB) >= __fmul_rn(0.695f, fmaxf(aA,aB)))
                        if (iou_sup(A, aA, cbox[c2], aB)) m |= 1ull << c2;
                }
            }
            #pragma unroll
            for (int off=8; off>0; off>>=1)
                m |= __shfl_xor_sync(FULL, m, off);
            if ((lane & 15)==0) s_mat[c] = m;
        }

        // ---- phase B2: warp-per-candidate, flat scan over 3x3 cell lists
        {
            int spillN = s_spillCnt;
            for (int cc = wid; cc < CHUNK; cc += 32){
                bool activeC = (cc < n);
                bool f = false;
                if (activeC){
                    float4 A = cbox[cc];
                    float aA = carea[cc];
                    int wb = cwb[cc], hb = chb[cc];
                    // always-9 cells (clamped; duplicates at borders are harmless)
                    int w0 = max(wb-1,0), w1 = wb, w2c = min(wb+1,NBW-1);
                    int h0 = max(hb-1,0), h1 = hb, h2c = min(hb+1,NBH-1);
                    int cell0 = w0 *NBH + h0,  cell1 = w0 *NBH + h1,  cell2 = w0 *NBH + h2c;
                    int cell3 = w1 *NBH + h0,  cell4 = w1 *NBH + h1,  cell5 = w1 *NBH + h2c;
                    int cell6 = w2c*NBH + h0,  cell7 = w2c*NBH + h1,  cell8 = w2c*NBH + h2c;
                    // independent count loads (pipelined)
                    int L0=s_bcnt[cell0], L1=s_bcnt[cell1], L2=s_bcnt[cell2];
                    int L3=s_bcnt[cell3], L4=s_bcnt[cell4], L5=s_bcnt[cell5];
                    int L6=s_bcnt[cell6], L7=s_bcnt[cell7], L8=s_bcnt[cell8];
                    int cum1=L0,        cum2=cum1+L1, cum3=cum2+L2;
                    int cum4=cum3+L3,   cum5=cum4+L4, cum6=cum5+L5;
                    int cum7=cum6+L6,   cum8=cum7+L7;
                    int tot = cum8+L8;
                    int b0c=cell0*BINCAP, b1c=cell1*BINCAP, b2c=cell2*BINCAP;
                    int b3c=cell3*BINCAP, b4c=cell4*BINCAP, b5c=cell5*BINCAP;
                    int b6c=cell6*BINCAP, b7c=cell7*BINCAP, b8c=cell8*BINCAP;

                    for (int basei=0; basei<tot; basei+=32){
                        int flat = basei + lane;
                        bool t = false;
                        if (flat < tot && !f){
                            // flat -> (cell base, offset) via SEL chain
                            int cbase = b8c, rel = flat - cum8;
                            if (flat < cum8){ cbase = b7c; rel = flat - cum7; }
                            if (flat < cum7){ cbase = b6c; rel = flat - cum6; }
                            if (flat < cum6){ cbase = b5c; rel = flat - cum5; }
                            if (flat < cum5){ cbase = b4c; rel = flat - cum4; }
                            if (flat < cum4){ cbase = b3c; rel = flat - cum3; }
                            if (flat < cum3){ cbase = b2c; rel = flat - cum2; }
                            if (flat < cum2){ cbase = b1c; rel = flat - cum1; }
                            if (flat < cum1){ cbase = b0c; rel = flat; }
                            int kj = cells[cbase + rel];
                            float aB = ka[kj];
                            if (fminf(aA,aB) >= __fmul_rn(0.695f, fmaxf(aA,aB)))
                                t = iou_sup(A, aA, kb[kj], aB);
                        }
                        f |= t;
                        if (__any_sync(FULL, f)) break;
                    }
                    // spill list (normally empty)
                    if (!__any_sync(FULL, f)){
                        for (int j=lane; __any_sync(FULL, j<spillN); j+=32){
                            bool t=false;
                            if (j < spillN && !f){
                                int kj = spill[j];
                                float aB = ka[kj];
                                if (fminf(aA,aB) >= __fmul_rn(0.695f, fmaxf(aA,aB)))
                                    t = iou_sup(A, aA, kb[kj], aB);
                            }
                            f |= t;
                            if (__any_sync(FULL, f)) break;
                        }
                    }
                }
                bool supC = __any_sync(FULL, f);
                if (lane==0) s_sup[cc] = supC ? 1 : 0;
            }
        }
        __syncthreads();                       // (2)

        // ---- phase C: warp-0 register-resident greedy resolve
        if (wid==0){
            unsigned lo = __ballot_sync(FULL, s_sup[lane] != 0);
            unsigned hi = __ballot_sync(FULL, s_sup[lane+32] != 0);
            unsigned long long sup = (unsigned long long)lo |
                                     ((unsigned long long)hi << 32);
            unsigned long long m0 = s_mat[lane];
            unsigned long long m1 = s_mat[lane+32];
            unsigned long long rem = ~sup;
            if (n < 64) rem &= (1ull<<n) - 1ull;
            int nn = 0;
            while (rem != 0ull && kept+nn < POST){
                int c = __ffsll((long long)rem) - 1;
                if (lane==0) s_new[nn] = c;
                nn++;
                unsigned long long mc = __shfl_sync(FULL, (c<32)? m0 : m1, c & 31);
                rem &= ~mc;
                rem &= ~(1ull << c);
            }
            if (lane==0){ s_nn = nn; s_kept = kept + nn; }
        }
        __syncthreads();                       // (3)

        // ---- phase D: append keeps into cells + write outputs
        int nn = s_nn;
        if (tid < nn){
            int cc = s_new[tid];
            float4 bx = cbox[cc];
            float a  = carea[cc];
            int ki = kept + tid;
            kb[ki] = bx;
            ka[ki] = a;
            int cell = (int)cwb[cc]*NBH + (int)chb[cc];
            int slot = atomicAdd(&s_bcnt[cell], 1);
            if (slot < BINCAP){
                cells[cell*BINCAP + slot] = (unsigned short)ki;
            } else {
                atomicSub(&s_bcnt[cell], 1);
                int sp = atomicAdd(&s_spillCnt, 1);
                spill[sp] = (unsigned short)ki;
            }
            int row = b*POST + ki;
            ((float4*)outRois)[row] = bx;
            if (writeMask) outMask[row] = 1.0f;
        }
        __syncthreads();                       // (4)
    }

    // ---- zero-fill tail
    int kept = s_kept;
    for (int rrow = kept + tid; rrow < POST; rrow += NMS_THREADS){
        int row = b*POST + rrow;
        ((float4*)outRois)[row] = make_float4(0.f,0.f,0.f,0.f);
        if (writeMask) outMask[row] = 0.f;
    }
}

// ---------------------------------------------------------------- launch
extern "C" void kernel_launch(void* const* d_in, const int* in_sizes, int n_in,
                              void* d_out, int out_size)
{
    (void)in_sizes; (void)n_in;
    const float4* anchors = (const float4*)d_in[0];
    const float*  cls     = (const float*)d_in[1];
    const float4* pred    = (const float4*)d_in[2];
    float* out = (float*)d_out;

    cudaFuncSetAttribute(k_nms, cudaFuncAttributeMaxDynamicSharedMemorySize, SMEM_NMS);

    int total = BATCH*N_ANCH;
    k_decode<<<(total+255)/256, 256>>>(anchors, cls, pred);
    k_select<<<BATCH, 1024>>>();

    int writeMask = (out_size >= BATCH*POST*5) ? 1 : 0;
    k_nms<<<BATCH, NMS_THREADS, SMEM_NMS>>>(out, out + BATCH*POST*4, writeMask);
}